// round 8
// baseline (speedup 1.0000x reference)
#include <cuda_runtime.h>

#define SEQ     262144
#define HID     20
#define INP     9
#define CH      448            // output chunk per block
#define WARM    64             // warmup steps
#define GROUP   16             // sync granularity (steps)
#define RING0   64             // xg1 ring depth (4 groups)
#define RING12  32             // h1 / l2-preact ring depth (2 groups)
#define RINGH   64             // h2 ring depth (4 groups)
#define AHEAD   48             // xproj runs 3 groups ahead
#define NBLK    ((SEQ + CH - 1) / CH)   // 586 blocks

typedef unsigned long long u64;

__device__ __forceinline__ u64 pk2(float lo, float hi) {
    u64 r; asm("mov.b64 %0,{%1,%2};" : "=l"(r) : "f"(lo), "f"(hi)); return r;
}
__device__ __forceinline__ void up2(u64 v, float& lo, float& hi) {
    asm("mov.b64 {%0,%1},%2;" : "=f"(lo), "=f"(hi) : "l"(v));
}
__device__ __forceinline__ u64 fma2(u64 a, u64 b, u64 c) {
    u64 d; asm("fma.rn.f32x2 %0,%1,%2,%3;" : "=l"(d) : "l"(a), "l"(b), "l"(c)); return d;
}
__device__ __forceinline__ float sigf(float v) {
    return __fdividef(1.f, 1.f + __expf(-v));
}
__device__ __forceinline__ float tanhf_(float v) {
    return 1.f - __fdividef(2.f, __expf(2.f * v) + 1.f);
}

__global__ void __launch_bounds__(128, 4) lstm_kernel(
    const float* __restrict__ x,
    const float* __restrict__ w_ih1, const float* __restrict__ w_hh1, const float* __restrict__ b1,
    const float* __restrict__ w_ih2, const float* __restrict__ w_hh2, const float* __restrict__ b2,
    const float* __restrict__ w_p,  const float* __restrict__ b_p,
    float* __restrict__ out)
{
    __shared__ __align__(16) float ring0[RING0][HID][4];   // l1 input preacts (incl b1)
    __shared__ __align__(16) float ring1[RING12][HID];     // h1
    __shared__ __align__(16) float ring2[RING12][HID][4];  // l2 input preacts (incl b2)
    __shared__ __align__(16) float ringh[RINGH][HID];      // h2
    __shared__ __align__(16) float hsh1[2][HID + 2];       // S1 h broadcast (double-buffered)
    __shared__ __align__(16) float hsh3[2][HID + 2];       // S3 h broadcast (double-buffered)
    __shared__ int f0x, f1, f2, f3, f4;

    const int tid  = threadIdx.x;
    const int warp = tid >> 5;
    const int lane = tid & 31;
    const int k    = (lane < HID) ? lane : (HID - 1);
    const bool active = (lane < HID);
    const int stage = (warp + (int)(blockIdx.x / 148)) & 3;

    if (tid == 0) { f0x = -1; f1 = -1; f2 = -1; f3 = -1; f4 = -1; }
    __syncthreads();

    const int blk       = blockIdx.x;
    const int out_begin = blk * CH;
    const int out_end   = (out_begin + CH < SEQ) ? (out_begin + CH) : SEQ;
    const int start     = (blk == 0) ? 0 : (out_begin - WARM);
    const int nsteps    = out_end - start;        // multiple of GROUP
    const int ngroups   = nsteps >> 4;

    volatile int* vf0 = &f0x;
    volatile int* vf1 = &f1;
    volatile int* vf2 = &f2;
    volatile int* vf3 = &f3;
    volatile int* vf4 = &f4;

    if (stage == 0) {
        // ===== S0: l1 x-projection (AHEAD ahead) + output projection =====
        u64   wi1p[4][4];
        float wi1s[4], bb1[4];
        #pragma unroll
        for (int g = 0; g < 4; g++) {
            const int row = g * HID + k;
            #pragma unroll
            for (int i = 0; i < 4; i++)
                wi1p[g][i] = pk2(w_ih1[row * INP + 2 * i], w_ih1[row * INP + 2 * i + 1]);
            wi1s[g] = w_ih1[row * INP + 8];
            bb1[g]  = b1[row];
        }
        const float wp = active ? w_p[k] : 0.f;
        const float bp = b_p[0];

        auto xproj = [&](int ss) {
            const int base = (start + ss) * INP;
            float xv[INP];
            #pragma unroll
            for (int j = 0; j < INP; j++) xv[j] = x[base + j];
            u64 xp[4];
            #pragma unroll
            for (int i = 0; i < 4; i++) xp[i] = pk2(xv[2 * i], xv[2 * i + 1]);
            float pr[4];
            #pragma unroll
            for (int g = 0; g < 4; g++) {
                u64 a = pk2(bb1[g], 0.f);
                #pragma unroll
                for (int i = 0; i < 4; i++) a = fma2(xp[i], wi1p[g][i], a);
                float lo, hi; up2(a, lo, hi);
                pr[g] = fmaf(xv[8], wi1s[g], lo + hi);
            }
            if (active)
                *(float4*)&ring0[ss & (RING0 - 1)][k][0] = make_float4(pr[0], pr[1], pr[2], pr[3]);
        };

        // prefill groups 0..2
        for (int s = 0; s < AHEAD && s < nsteps; s++) xproj(s);
        __threadfence_block();
        if (lane == 0) *vf0 = AHEAD / GROUP - 1;

        for (int gl = 0; gl < ngroups; gl++) {
            // xproj group gl+3 (ring0 depth 4: overwrites group gl-1)
            while (*vf1 < gl - 1) { __nanosleep(32); }
            const int xg = gl + AHEAD / GROUP;
            if (xg < ngroups) {
                const int sb = xg << 4;
                #pragma unroll 2
                for (int i = 0; i < GROUP; i++) xproj(sb + i);
            }
            __threadfence_block();
            if (lane == 0) *vf0 = xg;

            // output projection for group gl (skip pure-warmup groups)
            const int tg = start + (gl << 4);
            if (tg + GROUP - 1 >= out_begin) {
                while (*vf3 < gl) { __nanosleep(32); }
                __threadfence_block();
                #pragma unroll 2
                for (int i = 0; i < GROUP; i++) {
                    const int t = tg + i;
                    if (t >= out_begin) {
                        const int sl = ((gl << 4) + i) & (RINGH - 1);
                        float p = active ? (wp * ringh[sl][k]) : 0.f;
                        #pragma unroll
                        for (int off = 16; off; off >>= 1)
                            p += __shfl_down_sync(0xffffffffu, p, off);
                        if (lane == 0) out[t] = p + bp;
                    }
                }
            }
            __threadfence_block();
            if (lane == 0) *vf4 = gl;
        }
    } else if (stage == 1) {
        // ===== S1: layer-1 recurrence (smem h-broadcast, no shfl) =====
        u64 whhp[4][HID / 2];
        #pragma unroll
        for (int g = 0; g < 4; g++) {
            const int row = g * HID + k;
            #pragma unroll
            for (int i = 0; i < HID / 2; i++)
                whhp[g][i] = pk2(w_hh1[row * HID + 2 * i], w_hh1[row * HID + 2 * i + 1]);
        }
        float h = 0.f, c = 0.f;
        float4 pre;

        for (int s = 0; s < nsteps; s++) {
            if ((s & (GROUP - 1)) == 0) {
                const int g = s >> 4;
                while (*vf0 < g) { __nanosleep(32); }                   // xproj ready
                while (*vf2 < g - RING12 / GROUP) { __nanosleep(32); }  // ring1 free
                __threadfence_block();
                pre = *(const float4*)&ring0[s & (RING0 - 1)][k][0];
            }

            // broadcast h via double-buffered smem row
            if (active) hsh1[s & 1][k] = h;
            __syncwarp();
            const u64* hp = (const u64*)&hsh1[s & 1][0];

            u64 acc[4];
            acc[0] = pk2(pre.x, 0.f); acc[1] = pk2(pre.y, 0.f);
            acc[2] = pk2(pre.z, 0.f); acc[3] = pk2(pre.w, 0.f);
            #pragma unroll
            for (int i = 0; i < HID / 2; i++) {
                const u64 hpi = hp[i];
                #pragma unroll
                for (int g = 0; g < 4; g++) acc[g] = fma2(hpi, whhp[g][i], acc[g]);
            }
            // prefetch next step's preacts (within group; boundary reloads after wait)
            if ((s & (GROUP - 1)) != GROUP - 1)
                pre = *(const float4*)&ring0[(s + 1) & (RING0 - 1)][k][0];

            float pa[4];
            #pragma unroll
            for (int g = 0; g < 4; g++) { float lo, hi; up2(acc[g], lo, hi); pa[g] = lo + hi; }

            const float ig = sigf(pa[0]);
            const float fg = sigf(pa[1]);
            const float gg = tanhf_(pa[2]);
            const float og = sigf(pa[3]);
            c = fg * c + ig * gg;
            h = og * tanhf_(c);

            if (active) ring1[s & (RING12 - 1)][k] = h;

            if ((s & (GROUP - 1)) == GROUP - 1) {
                __threadfence_block();
                if (lane == 0) *vf1 = s >> 4;
            }
        }
    } else if (stage == 2) {
        // ===== S2: layer-2 input projection =====
        u64   wi2p[4][HID / 2];
        float bb2[4];
        #pragma unroll
        for (int g = 0; g < 4; g++) {
            const int row = g * HID + k;
            #pragma unroll
            for (int i = 0; i < HID / 2; i++)
                wi2p[g][i] = pk2(w_ih2[row * HID + 2 * i], w_ih2[row * HID + 2 * i + 1]);
            bb2[g] = b2[row];
        }

        for (int s = 0; s < nsteps; s++) {
            if ((s & (GROUP - 1)) == 0) {
                const int g = s >> 4;
                while (*vf1 < g) { __nanosleep(32); }                   // h1 ready
                while (*vf3 < g - RING12 / GROUP) { __nanosleep(32); }  // ring2 free
                __threadfence_block();
            }
            const int sl = s & (RING12 - 1);
            const u64* hp = (const u64*)&ring1[sl][0];

            u64 acc[4];
            #pragma unroll
            for (int g = 0; g < 4; g++) acc[g] = pk2(bb2[g], 0.f);
            #pragma unroll
            for (int i = 0; i < HID / 2; i++) {
                const u64 hpi = hp[i];
                #pragma unroll
                for (int g = 0; g < 4; g++) acc[g] = fma2(hpi, wi2p[g][i], acc[g]);
            }
            float pr[4];
            #pragma unroll
            for (int g = 0; g < 4; g++) { float lo, hi; up2(acc[g], lo, hi); pr[g] = lo + hi; }
            if (active)
                *(float4*)&ring2[sl][k][0] = make_float4(pr[0], pr[1], pr[2], pr[3]);

            if ((s & (GROUP - 1)) == GROUP - 1) {
                __threadfence_block();
                if (lane == 0) *vf2 = s >> 4;
            }
        }
    } else {
        // ===== S3: layer-2 recurrence (smem h-broadcast, no shfl) =====
        u64 whhp[4][HID / 2];
        #pragma unroll
        for (int g = 0; g < 4; g++) {
            const int row = g * HID + k;
            #pragma unroll
            for (int i = 0; i < HID / 2; i++)
                whhp[g][i] = pk2(w_hh2[row * HID + 2 * i], w_hh2[row * HID + 2 * i + 1]);
        }
        float h = 0.f, c = 0.f;
        float4 pre;

        for (int s = 0; s < nsteps; s++) {
            if ((s & (GROUP - 1)) == 0) {
                const int g = s >> 4;
                while (*vf2 < g) { __nanosleep(32); }                   // l2 preacts ready
                while (*vf4 < g - RINGH / GROUP) { __nanosleep(32); }   // ringh free
                __threadfence_block();
                pre = *(const float4*)&ring2[s & (RING12 - 1)][k][0];
            }

            if (active) hsh3[s & 1][k] = h;
            __syncwarp();
            const u64* hp = (const u64*)&hsh3[s & 1][0];

            u64 acc[4];
            acc[0] = pk2(pre.x, 0.f); acc[1] = pk2(pre.y, 0.f);
            acc[2] = pk2(pre.z, 0.f); acc[3] = pk2(pre.w, 0.f);
            #pragma unroll
            for (int i = 0; i < HID / 2; i++) {
                const u64 hpi = hp[i];
                #pragma unroll
                for (int g = 0; g < 4; g++) acc[g] = fma2(hpi, whhp[g][i], acc[g]);
            }
            if ((s & (GROUP - 1)) != GROUP - 1)
                pre = *(const float4*)&ring2[(s + 1) & (RING12 - 1)][k][0];

            float pa[4];
            #pragma unroll
            for (int g = 0; g < 4; g++) { float lo, hi; up2(acc[g], lo, hi); pa[g] = lo + hi; }

            const float ig = sigf(pa[0]);
            const float fg = sigf(pa[1]);
            const float gg = tanhf_(pa[2]);
            const float og = sigf(pa[3]);
            c = fg * c + ig * gg;
            h = og * tanhf_(c);

            if (active) ringh[s & (RINGH - 1)][k] = h;

            if ((s & (GROUP - 1)) == GROUP - 1) {
                __threadfence_block();
                if (lane == 0) *vf3 = s >> 4;
            }
        }
    }
}

extern "C" void kernel_launch(void* const* d_in, const int* in_sizes, int n_in,
                              void* d_out, int out_size)
{
    const float* x     = (const float*)d_in[0];
    const float* w_ih1 = (const float*)d_in[1];
    const float* w_hh1 = (const float*)d_in[2];
    const float* b1    = (const float*)d_in[3];
    const float* w_ih2 = (const float*)d_in[4];
    const float* w_hh2 = (const float*)d_in[5];
    const float* b2    = (const float*)d_in[6];
    const float* w_p   = (const float*)d_in[7];
    const float* b_p   = (const float*)d_in[8];
    float* out = (float*)d_out;

    lstm_kernel<<<NBLK, 128>>>(x, w_ih1, w_hh1, b1, w_ih2, w_hh2, b2, w_p, b_p, out);
}

// round 9
// speedup vs baseline: 1.0359x; 1.0359x over previous
#include <cuda_runtime.h>

#define SEQ     262144
#define HID     20
#define INP     9
#define CH      448            // output chunk per block
#define WARM    64             // warmup steps
#define GROUP   16             // sync granularity (steps)
#define RING0   64             // xg1 ring depth (4 groups)
#define RING12  32             // h1 / l2-preact ring depth (2 groups)
#define RINGH   64             // h2 ring depth (4 groups)
#define AHEAD   48             // xproj runs 3 groups ahead
#define NBLK    ((SEQ + CH - 1) / CH)   // 586 blocks

typedef unsigned long long u64;

__device__ __forceinline__ u64 pk2(float lo, float hi) {
    u64 r; asm("mov.b64 %0,{%1,%2};" : "=l"(r) : "f"(lo), "f"(hi)); return r;
}
__device__ __forceinline__ void up2(u64 v, float& lo, float& hi) {
    asm("mov.b64 {%0,%1},%2;" : "=f"(lo), "=f"(hi) : "l"(v));
}
__device__ __forceinline__ u64 fma2(u64 a, u64 b, u64 c) {
    u64 d; asm("fma.rn.f32x2 %0,%1,%2,%3;" : "=l"(d) : "l"(a), "l"(b), "l"(c)); return d;
}
__device__ __forceinline__ float sigf(float v) {
    return __fdividef(1.f, 1.f + __expf(-v));
}
__device__ __forceinline__ float tanhf_(float v) {
    return 1.f - __fdividef(2.f, __expf(2.f * v) + 1.f);
}

__global__ void __launch_bounds__(128, 4) lstm_kernel(
    const float* __restrict__ x,
    const float* __restrict__ w_ih1, const float* __restrict__ w_hh1, const float* __restrict__ b1,
    const float* __restrict__ w_ih2, const float* __restrict__ w_hh2, const float* __restrict__ b2,
    const float* __restrict__ w_p,  const float* __restrict__ b_p,
    float* __restrict__ out)
{
    __shared__ __align__(16) float ring0[RING0][HID][4];   // l1 input preacts (incl b1)
    __shared__ __align__(16) float ring1[RING12][HID];     // h1
    __shared__ __align__(16) float ring2[RING12][HID][4];  // l2 input preacts (incl b2)
    __shared__ __align__(16) float ringh[RINGH][HID];      // h2
    __shared__ __align__(16) float xbuf[2][GROUP * INP];   // staged x, double-buffered per group
    __shared__ int f0x, f1, f2, f3, f4;

    const int tid  = threadIdx.x;
    const int warp = tid >> 5;
    const int lane = tid & 31;
    const int k    = (lane < HID) ? lane : (HID - 1);
    const bool active = (lane < HID);
    const int stage = (warp + (int)(blockIdx.x / 148)) & 3;

    if (tid == 0) { f0x = -1; f1 = -1; f2 = -1; f3 = -1; f4 = -1; }
    __syncthreads();

    const int blk       = blockIdx.x;
    const int out_begin = blk * CH;
    const int out_end   = (out_begin + CH < SEQ) ? (out_begin + CH) : SEQ;
    const int start     = (blk == 0) ? 0 : (out_begin - WARM);
    const int nsteps    = out_end - start;        // multiple of GROUP
    const int ngroups   = nsteps >> 4;

    volatile int* vf0 = &f0x;
    volatile int* vf1 = &f1;
    volatile int* vf2 = &f2;
    volatile int* vf3 = &f3;
    volatile int* vf4 = &f4;

    if (stage == 0) {
        // ===== S0: l1 x-projection (AHEAD ahead, smem-staged x) + output projection =====
        u64   wi1p[4][4];
        float wi1s[4], bb1[4];
        #pragma unroll
        for (int g = 0; g < 4; g++) {
            const int row = g * HID + k;
            #pragma unroll
            for (int i = 0; i < 4; i++)
                wi1p[g][i] = pk2(w_ih1[row * INP + 2 * i], w_ih1[row * INP + 2 * i + 1]);
            wi1s[g] = w_ih1[row * INP + 8];
            bb1[g]  = b1[row];
        }
        const float wp = active ? w_p[k] : 0.f;
        const float bp = b_p[0];

        // core projection from 9 x-values
        auto xcore = [&](const float* xv, int slot) {
            u64 xp[4];
            #pragma unroll
            for (int i = 0; i < 4; i++) xp[i] = pk2(xv[2 * i], xv[2 * i + 1]);
            float pr[4];
            #pragma unroll
            for (int g = 0; g < 4; g++) {
                u64 a = pk2(bb1[g], 0.f);
                #pragma unroll
                for (int i = 0; i < 4; i++) a = fma2(xp[i], wi1p[g][i], a);
                float lo, hi; up2(a, lo, hi);
                pr[g] = fmaf(xv[8], wi1s[g], lo + hi);
            }
            if (active)
                *(float4*)&ring0[slot][k][0] = make_float4(pr[0], pr[1], pr[2], pr[3]);
        };

        // stage one group's x (144 floats = 36 float4) into xbuf[buf]
        auto stagex = [&](int xg) {
            const int buf = xg & 1;
            const float4* src = (const float4*)(x + (start + (xg << 4)) * INP);
            float4* dst = (float4*)&xbuf[buf][0];
            if (lane < 32) dst[lane] = src[lane];          // f4 0..31
            if (lane < 4)  dst[32 + lane] = src[32 + lane]; // f4 32..35
        };

        // prefill: xproj groups 0..2 straight from global
        for (int s = 0; s < AHEAD && s < nsteps; s++) {
            const int base = (start + s) * INP;
            float xv[INP];
            #pragma unroll
            for (int j = 0; j < INP; j++) xv[j] = x[base + j];
            xcore(xv, s & (RING0 - 1));
        }
        __threadfence_block();
        if (lane == 0) *vf0 = AHEAD / GROUP - 1;

        // stage x for group 3 (first staged group)
        if (AHEAD / GROUP < ngroups) stagex(AHEAD / GROUP);
        __syncwarp();

        for (int gl = 0; gl < ngroups; gl++) {
            const int xg = gl + AHEAD / GROUP;
            // issue next group's x stage early (latency hidden behind this group's work)
            if (xg + 1 < ngroups) stagex(xg + 1);

            while (*vf1 < gl - 1) { }
            if (xg < ngroups) {
                const float* xb = &xbuf[xg & 1][0];
                #pragma unroll 2
                for (int i = 0; i < GROUP; i++) {
                    float xv[INP];
                    #pragma unroll
                    for (int j = 0; j < INP; j++) xv[j] = xb[i * INP + j];
                    xcore(xv, ((xg << 4) + i) & (RING0 - 1));
                }
            }
            __threadfence_block();
            if (lane == 0) *vf0 = xg;

            // output projection for group gl (skip pure-warmup groups)
            const int tg = start + (gl << 4);
            if (tg + GROUP - 1 >= out_begin) {
                while (*vf3 < gl) { }
                __threadfence_block();
                #pragma unroll 2
                for (int i = 0; i < GROUP; i++) {
                    const int t = tg + i;
                    if (t >= out_begin) {
                        const int sl = ((gl << 4) + i) & (RINGH - 1);
                        float p = active ? (wp * ringh[sl][k]) : 0.f;
                        #pragma unroll
                        for (int off = 16; off; off >>= 1)
                            p += __shfl_down_sync(0xffffffffu, p, off);
                        if (lane == 0) out[t] = p + bp;
                    }
                }
            }
            __threadfence_block();
            if (lane == 0) *vf4 = gl;
            __syncwarp();   // xbuf stage for xg+1 complete before next iteration reads it
        }
    } else if (stage == 1) {
        // ===== S1: layer-1 recurrence (shfl broadcast) =====
        u64 whhp[4][HID / 2];
        #pragma unroll
        for (int g = 0; g < 4; g++) {
            const int row = g * HID + k;
            #pragma unroll
            for (int i = 0; i < HID / 2; i++)
                whhp[g][i] = pk2(w_hh1[row * HID + 2 * i], w_hh1[row * HID + 2 * i + 1]);
        }
        float h = 0.f, c = 0.f;
        float4 pre;

        for (int s = 0; s < nsteps; s++) {
            if ((s & (GROUP - 1)) == 0) {
                const int g = s >> 4;
                while (*vf0 < g) { }                   // xproj ready
                while (*vf2 < g - RING12 / GROUP) { }  // ring1 free
                __threadfence_block();
                pre = *(const float4*)&ring0[s & (RING0 - 1)][k][0];
            }

            u64 acc[4];
            acc[0] = pk2(pre.x, 0.f); acc[1] = pk2(pre.y, 0.f);
            acc[2] = pk2(pre.z, 0.f); acc[3] = pk2(pre.w, 0.f);
            #pragma unroll
            for (int i = 0; i < HID / 2; i++) {
                const float h0 = __shfl_sync(0xffffffffu, h, 2 * i);
                const float h1 = __shfl_sync(0xffffffffu, h, 2 * i + 1);
                const u64 hp = pk2(h0, h1);
                #pragma unroll
                for (int g = 0; g < 4; g++) acc[g] = fma2(hp, whhp[g][i], acc[g]);
            }
            if ((s & (GROUP - 1)) != GROUP - 1)
                pre = *(const float4*)&ring0[(s + 1) & (RING0 - 1)][k][0];

            float pa[4];
            #pragma unroll
            for (int g = 0; g < 4; g++) { float lo, hi; up2(acc[g], lo, hi); pa[g] = lo + hi; }

            const float ig = sigf(pa[0]);
            const float fg = sigf(pa[1]);
            const float gg = tanhf_(pa[2]);
            const float og = sigf(pa[3]);
            c = fg * c + ig * gg;
            h = og * tanhf_(c);

            if (active) ring1[s & (RING12 - 1)][k] = h;

            if ((s & (GROUP - 1)) == GROUP - 1) {
                __threadfence_block();
                if (lane == 0) *vf1 = s >> 4;
            }
        }
    } else if (stage == 2) {
        // ===== S2: layer-2 input projection =====
        u64   wi2p[4][HID / 2];
        float bb2[4];
        #pragma unroll
        for (int g = 0; g < 4; g++) {
            const int row = g * HID + k;
            #pragma unroll
            for (int i = 0; i < HID / 2; i++)
                wi2p[g][i] = pk2(w_ih2[row * HID + 2 * i], w_ih2[row * HID + 2 * i + 1]);
            bb2[g] = b2[row];
        }

        for (int s = 0; s < nsteps; s++) {
            if ((s & (GROUP - 1)) == 0) {
                const int g = s >> 4;
                while (*vf1 < g) { }                   // h1 ready
                while (*vf3 < g - RING12 / GROUP) { }  // ring2 free
                __threadfence_block();
            }
            const int sl = s & (RING12 - 1);
            const u64* hp = (const u64*)&ring1[sl][0];

            u64 acc[4];
            #pragma unroll
            for (int g = 0; g < 4; g++) acc[g] = pk2(bb2[g], 0.f);
            #pragma unroll
            for (int i = 0; i < HID / 2; i++) {
                const u64 hpi = hp[i];
                #pragma unroll
                for (int g = 0; g < 4; g++) acc[g] = fma2(hpi, wi2p[g][i], acc[g]);
            }
            float pr[4];
            #pragma unroll
            for (int g = 0; g < 4; g++) { float lo, hi; up2(acc[g], lo, hi); pr[g] = lo + hi; }
            if (active)
                *(float4*)&ring2[sl][k][0] = make_float4(pr[0], pr[1], pr[2], pr[3]);

            if ((s & (GROUP - 1)) == GROUP - 1) {
                __threadfence_block();
                if (lane == 0) *vf2 = s >> 4;
            }
        }
    } else {
        // ===== S3: layer-2 recurrence (shfl broadcast) =====
        u64 whhp[4][HID / 2];
        #pragma unroll
        for (int g = 0; g < 4; g++) {
            const int row = g * HID + k;
            #pragma unroll
            for (int i = 0; i < HID / 2; i++)
                whhp[g][i] = pk2(w_hh2[row * HID + 2 * i], w_hh2[row * HID + 2 * i + 1]);
        }
        float h = 0.f, c = 0.f;
        float4 pre;

        for (int s = 0; s < nsteps; s++) {
            if ((s & (GROUP - 1)) == 0) {
                const int g = s >> 4;
                while (*vf2 < g) { }                   // l2 preacts ready
                while (*vf4 < g - RINGH / GROUP) { }   // ringh free
                __threadfence_block();
                pre = *(const float4*)&ring2[s & (RING12 - 1)][k][0];
            }

            u64 acc[4];
            acc[0] = pk2(pre.x, 0.f); acc[1] = pk2(pre.y, 0.f);
            acc[2] = pk2(pre.z, 0.f); acc[3] = pk2(pre.w, 0.f);
            #pragma unroll
            for (int i = 0; i < HID / 2; i++) {
                const float h0 = __shfl_sync(0xffffffffu, h, 2 * i);
                const float h1 = __shfl_sync(0xffffffffu, h, 2 * i + 1);
                const u64 hp = pk2(h0, h1);
                #pragma unroll
                for (int g = 0; g < 4; g++) acc[g] = fma2(hp, whhp[g][i], acc[g]);
            }
            if ((s & (GROUP - 1)) != GROUP - 1)
                pre = *(const float4*)&ring2[(s + 1) & (RING12 - 1)][k][0];

            float pa[4];
            #pragma unroll
            for (int g = 0; g < 4; g++) { float lo, hi; up2(acc[g], lo, hi); pa[g] = lo + hi; }

            const float ig = sigf(pa[0]);
            const float fg = sigf(pa[1]);
            const float gg = tanhf_(pa[2]);
            const float og = sigf(pa[3]);
            c = fg * c + ig * gg;
            h = og * tanhf_(c);

            if (active) ringh[s & (RINGH - 1)][k] = h;

            if ((s & (GROUP - 1)) == GROUP - 1) {
                __threadfence_block();
                if (lane == 0) *vf3 = s >> 4;
            }
        }
    }
}

extern "C" void kernel_launch(void* const* d_in, const int* in_sizes, int n_in,
                              void* d_out, int out_size)
{
    const float* x     = (const float*)d_in[0];
    const float* w_ih1 = (const float*)d_in[1];
    const float* w_hh1 = (const float*)d_in[2];
    const float* b1    = (const float*)d_in[3];
    const float* w_ih2 = (const float*)d_in[4];
    const float* w_hh2 = (const float*)d_in[5];
    const float* b2    = (const float*)d_in[6];
    const float* w_p   = (const float*)d_in[7];
    const float* b_p   = (const float*)d_in[8];
    float* out = (float*)d_out;

    lstm_kernel<<<NBLK, 128>>>(x, w_ih1, w_hh1, b1, w_ih2, w_hh2, b2, w_p, b_p, out);
}

// round 11
// speedup vs baseline: 1.4808x; 1.4295x over previous
#include <cuda_runtime.h>

#define SEQ    262144
#define HID    20
#define INP    9
#define CH     448
#define WARM   32
#define GROUP  16
#define R1     32               // h1 ring: 2 groups
#define RH     64               // h2 ring: 4 groups
#define RHP    22               // padded h2 row (bank-conflict-free outproj)
#define NCHUNK ((SEQ + CH - 1) / CH)     // 586
#define NBLK   ((NCHUNK + 1) / 2)        // 293 blocks * 2 chunks

typedef unsigned long long u64;

__device__ __forceinline__ u64 pk2(float lo, float hi) {
    u64 r; asm("mov.b64 %0,{%1,%2};" : "=l"(r) : "f"(lo), "f"(hi)); return r;
}
__device__ __forceinline__ void up2(u64 v, float& lo, float& hi) {
    asm("mov.b64 {%0,%1},%2;" : "=f"(lo), "=f"(hi) : "l"(v));
}
__device__ __forceinline__ u64 fma2(u64 a, u64 b, u64 c) {
    u64 d; asm("fma.rn.f32x2 %0,%1,%2,%3;" : "=l"(d) : "l"(a), "l"(b), "l"(c)); return d;
}
__device__ __forceinline__ float sigf(float v) {
    return __fdividef(1.f, 1.f + __expf(-v));
}
__device__ __forceinline__ float tanhf_(float v) {
    return 1.f - __fdividef(2.f, __expf(2.f * v) + 1.f);
}

__global__ void __launch_bounds__(128, 2) lstm_kernel(
    const float* __restrict__ x,
    const float* __restrict__ w_ih1, const float* __restrict__ w_hh1, const float* __restrict__ b1,
    const float* __restrict__ w_ih2, const float* __restrict__ w_hh2, const float* __restrict__ b2,
    const float* __restrict__ w_p,  const float* __restrict__ b_p,
    float* __restrict__ out)
{
    __shared__ __align__(16) float ring1[2][R1][HID];          // h1 per step
    __shared__ __align__(16) float ringh[2][RH][RHP];          // h2 per step (padded rows)
    __shared__ __align__(16) float xbuf[2][2][GROUP * INP];    // staged x per group
    __shared__ int fA[2], fB[2];

    const int tid  = threadIdx.x;
    const int warp = tid >> 5;
    const int lane = tid & 31;
    const int pidx = warp >> 1;        // chunk-pair within block
    const int role = warp & 1;         // 0 = A (layer1+io), 1 = B (layer2)
    const int chunk = blockIdx.x * 2 + pidx;
    const int k    = (lane < HID) ? lane : (HID - 1);
    const bool active = (lane < HID);

    if (tid == 0) { fA[0] = -1; fA[1] = -1; fB[0] = -1; fB[1] = -1; }
    __syncthreads();

    const int out_begin = chunk * CH;
    const int out_end   = (out_begin + CH < SEQ) ? (out_begin + CH) : SEQ;
    const int start     = (chunk == 0) ? 0 : (out_begin - WARM);
    const int nsteps    = out_end - start;          // multiple of GROUP
    const int ngroups   = nsteps >> 4;

    volatile int* vfA = &fA[pidx];
    volatile int* vfB = &fB[pidx];

    if (role == 0) {
        // ================= warp A: xproj -> layer-1 recurrence -> outproj =================
        u64   wi1p[4][4];
        float wi1s[4], bb1[4];
        u64   whhp[4][HID / 2];
        u64   wpp[HID / 2];
        #pragma unroll
        for (int g = 0; g < 4; g++) {
            const int row = g * HID + k;
            #pragma unroll
            for (int i = 0; i < 4; i++)
                wi1p[g][i] = pk2(w_ih1[row * INP + 2 * i], w_ih1[row * INP + 2 * i + 1]);
            wi1s[g] = w_ih1[row * INP + 8];
            bb1[g]  = b1[row];
            #pragma unroll
            for (int i = 0; i < HID / 2; i++)
                whhp[g][i] = pk2(w_hh1[row * HID + 2 * i], w_hh1[row * HID + 2 * i + 1]);
        }
        #pragma unroll
        for (int i = 0; i < HID / 2; i++)
            wpp[i] = pk2(w_p[2 * i], w_p[2 * i + 1]);
        const float bp = b_p[0];
        float h = 0.f, c = 0.f;

        auto stagex = [&](int xg) {
            const float4* src = (const float4*)(x + (start + (xg << 4)) * INP);
            float4* dst = (float4*)&xbuf[pidx][xg & 1][0];
            dst[lane] = src[lane];                    // float4 0..31
            if (lane < 4) dst[32 + lane] = src[32 + lane];  // float4 32..35
        };

        auto outgroup = [&](int og) {
            if (lane < GROUP) {
                const int t = start + (og << 4) + lane;
                if (t >= out_begin && t < out_end) {
                    const int sl = ((og << 4) + lane) & (RH - 1);
                    const u64* hp = (const u64*)&ringh[pidx][sl][0];
                    u64 a = pk2(0.f, 0.f);
                    #pragma unroll
                    for (int j = 0; j < HID / 2; j++) a = fma2(hp[j], wpp[j], a);
                    float lo, hi; up2(a, lo, hi);
                    out[t] = lo + hi + bp;
                }
            }
        };

        stagex(0);
        __syncwarp();

        for (int g = 0; g < ngroups; g++) {
            if (g + 1 < ngroups) stagex(g + 1);     // consumed next iter (after syncwarp)
            while (*vfB < g - 2) { }                // ring1 slots free
            __threadfence_block();

            const float* xb = &xbuf[pidx][g & 1][0];
            #pragma unroll 2
            for (int i = 0; i < GROUP; i++) {
                const int s = (g << 4) + i;
                float xv[INP];
                #pragma unroll
                for (int j = 0; j < INP; j++) xv[j] = xb[i * INP + j];

                // x projection (registers only)
                u64 xp[4];
                #pragma unroll
                for (int q = 0; q < 4; q++) xp[q] = pk2(xv[2 * q], xv[2 * q + 1]);
                float prg[4];
                #pragma unroll
                for (int gt = 0; gt < 4; gt++) {
                    u64 a = pk2(bb1[gt], 0.f);
                    #pragma unroll
                    for (int q = 0; q < 4; q++) a = fma2(xp[q], wi1p[gt][q], a);
                    float lo, hi; up2(a, lo, hi);
                    prg[gt] = fmaf(xv[8], wi1s[gt], lo + hi);
                }

                // layer-1 recurrence
                u64 acc[4];
                #pragma unroll
                for (int gt = 0; gt < 4; gt++) acc[gt] = pk2(prg[gt], 0.f);
                #pragma unroll
                for (int j = 0; j < HID / 2; j++) {
                    const float h0 = __shfl_sync(0xffffffffu, h, 2 * j);
                    const float h1v = __shfl_sync(0xffffffffu, h, 2 * j + 1);
                    const u64 hp = pk2(h0, h1v);
                    #pragma unroll
                    for (int gt = 0; gt < 4; gt++) acc[gt] = fma2(hp, whhp[gt][j], acc[gt]);
                }
                float pa[4];
                #pragma unroll
                for (int gt = 0; gt < 4; gt++) { float lo, hi; up2(acc[gt], lo, hi); pa[gt] = lo + hi; }

                const float ig = sigf(pa[0]);
                const float fg = sigf(pa[1]);
                const float gg = tanhf_(pa[2]);
                const float og = sigf(pa[3]);
                c = fg * c + ig * gg;
                h = og * tanhf_(c);

                if (active) ring1[pidx][s & (R1 - 1)][k] = h;
            }
            __threadfence_block();
            if (lane == 0) *vfA = g;

            // output projection for previous group (overlaps with B working on group g)
            if (g >= 1) {
                while (*vfB < g - 1) { }
                __threadfence_block();
                outgroup(g - 1);
            }
            __syncwarp();   // xbuf stage visibility
        }
        // final group's outputs
        while (*vfB < ngroups - 1) { }
        __threadfence_block();
        outgroup(ngroups - 1);
    } else {
        // ================= warp B: full layer-2 =================
        u64   wi2p[4][HID / 2], whh2p[4][HID / 2];
        float bb2[4];
        #pragma unroll
        for (int g = 0; g < 4; g++) {
            const int row = g * HID + k;
            #pragma unroll
            for (int i = 0; i < HID / 2; i++) {
                wi2p[g][i]  = pk2(w_ih2[row * HID + 2 * i], w_ih2[row * HID + 2 * i + 1]);
                whh2p[g][i] = pk2(w_hh2[row * HID + 2 * i], w_hh2[row * HID + 2 * i + 1]);
            }
            bb2[g] = b2[row];
        }
        float h = 0.f, c = 0.f;

        for (int g = 0; g < ngroups; g++) {
            while (*vfA < g) { }
            __threadfence_block();

            #pragma unroll 2
            for (int i = 0; i < GROUP; i++) {
                const int s = (g << 4) + i;
                const u64* h1p = (const u64*)&ring1[pidx][s & (R1 - 1)][0];

                u64 acc1[4], acc2[4];
                #pragma unroll
                for (int gt = 0; gt < 4; gt++) { acc1[gt] = pk2(bb2[gt], 0.f); acc2[gt] = pk2(0.f, 0.f); }

                #pragma unroll
                for (int j = 0; j < HID / 2; j++) {
                    const u64 hp1 = h1p[j];
                    #pragma unroll
                    for (int gt = 0; gt < 4; gt++) acc1[gt] = fma2(hp1, wi2p[gt][j], acc1[gt]);
                }
                #pragma unroll
                for (int j = 0; j < HID / 2; j++) {
                    const float h0 = __shfl_sync(0xffffffffu, h, 2 * j);
                    const float h1v = __shfl_sync(0xffffffffu, h, 2 * j + 1);
                    const u64 hp2 = pk2(h0, h1v);
                    #pragma unroll
                    for (int gt = 0; gt < 4; gt++) acc2[gt] = fma2(hp2, whh2p[gt][j], acc2[gt]);
                }
                float pa[4];
                #pragma unroll
                for (int gt = 0; gt < 4; gt++) {
                    float lo1, hi1, lo2, hi2;
                    up2(acc1[gt], lo1, hi1); up2(acc2[gt], lo2, hi2);
                    pa[gt] = (lo1 + hi1) + (lo2 + hi2);
                }

                const float ig = sigf(pa[0]);
                const float fg = sigf(pa[1]);
                const float gg = tanhf_(pa[2]);
                const float og = sigf(pa[3]);
                c = fg * c + ig * gg;
                h = og * tanhf_(c);

                if (active) ringh[pidx][s & (RH - 1)][k] = h;
            }
            __threadfence_block();
            if (lane == 0) *vfB = g;
        }
    }
}

extern "C" void kernel_launch(void* const* d_in, const int* in_sizes, int n_in,
                              void* d_out, int out_size)
{
    const float* x     = (const float*)d_in[0];
    const float* w_ih1 = (const float*)d_in[1];
    const float* w_hh1 = (const float*)d_in[2];
    const float* b1    = (const float*)d_in[3];
    const float* w_ih2 = (const float*)d_in[4];
    const float* w_hh2 = (const float*)d_in[5];
    const float* b2    = (const float*)d_in[6];
    const float* w_p   = (const float*)d_in[7];
    const float* b_p   = (const float*)d_in[8];
    float* out = (float*)d_out;

    lstm_kernel<<<NBLK, 128>>>(x, w_ih1, w_hh1, b1, w_ih2, w_hh2, b2, w_p, b_p, out);
}

// round 12
// speedup vs baseline: 1.7438x; 1.1776x over previous
#include <cuda_runtime.h>

#define SEQ    262144
#define HID    20
#define INP    9
#define CH     448
#define WARM   32
#define GROUP  16
#define R1     32               // h1 ring: 2 groups
#define RH     64               // h2 ring: 4 groups
#define RHP    22               // padded h2 row (bank-conflict-free outproj)
#define NCHUNK ((SEQ + CH - 1) / CH)     // 586
#define NBLK   ((NCHUNK + 1) / 2)        // 293 blocks * 2 chunks

typedef unsigned long long u64;

__device__ __forceinline__ u64 pk2(float lo, float hi) {
    u64 r; asm("mov.b64 %0,{%1,%2};" : "=l"(r) : "f"(lo), "f"(hi)); return r;
}
__device__ __forceinline__ void up2(u64 v, float& lo, float& hi) {
    asm("mov.b64 {%0,%1},%2;" : "=f"(lo), "=f"(hi) : "l"(v));
}
__device__ __forceinline__ u64 fma2(u64 a, u64 b, u64 c) {
    u64 d; asm("fma.rn.f32x2 %0,%1,%2,%3;" : "=l"(d) : "l"(a), "l"(b), "l"(c)); return d;
}
__device__ __forceinline__ float tanha(float v) {
    float r; asm("tanh.approx.f32 %0,%1;" : "=f"(r) : "f"(v)); return r;
}
__device__ __forceinline__ float sigf(float v) {
    return fmaf(0.5f, tanha(0.5f * v), 0.5f);
}
__device__ __forceinline__ float tanhf_(float v) {
    return tanha(v);
}

__global__ void __launch_bounds__(128, 2) lstm_kernel(
    const float* __restrict__ x,
    const float* __restrict__ w_ih1, const float* __restrict__ w_hh1, const float* __restrict__ b1,
    const float* __restrict__ w_ih2, const float* __restrict__ w_hh2, const float* __restrict__ b2,
    const float* __restrict__ w_p,  const float* __restrict__ b_p,
    float* __restrict__ out)
{
    __shared__ __align__(16) float ring1[2][R1][HID];          // h1 per step
    __shared__ __align__(16) float ringh[2][RH][RHP];          // h2 per step (padded rows)
    __shared__ __align__(16) float xbuf[2][2][GROUP * INP];    // staged x per group
    __shared__ int fA[2], fB[2];

    const int tid  = threadIdx.x;
    const int warp = tid >> 5;
    const int lane = tid & 31;
    const int pidx = warp >> 1;        // chunk-pair within block
    const int role = warp & 1;         // 0 = A (layer1+io), 1 = B (layer2)
    const int chunk = blockIdx.x * 2 + pidx;
    const int k    = (lane < HID) ? lane : (HID - 1);
    const bool active = (lane < HID);

    if (tid == 0) { fA[0] = -1; fA[1] = -1; fB[0] = -1; fB[1] = -1; }
    __syncthreads();

    const int out_begin = chunk * CH;
    const int out_end   = (out_begin + CH < SEQ) ? (out_begin + CH) : SEQ;
    const int start     = (chunk == 0) ? 0 : (out_begin - WARM);
    const int nsteps    = out_end - start;          // multiple of GROUP
    const int ngroups   = nsteps >> 4;

    volatile int* vfA = &fA[pidx];
    volatile int* vfB = &fB[pidx];

    if (role == 0) {
        // ================= warp A: xproj -> layer-1 recurrence -> outproj =================
        u64   wi1p[4][4];
        float wi1s[4], bb1[4];
        u64   whhp[4][HID / 2];
        u64   wpp[HID / 2];
        #pragma unroll
        for (int g = 0; g < 4; g++) {
            const int row = g * HID + k;
            #pragma unroll
            for (int i = 0; i < 4; i++)
                wi1p[g][i] = pk2(w_ih1[row * INP + 2 * i], w_ih1[row * INP + 2 * i + 1]);
            wi1s[g] = w_ih1[row * INP + 8];
            bb1[g]  = b1[row];
            #pragma unroll
            for (int i = 0; i < HID / 2; i++)
                whhp[g][i] = pk2(w_hh1[row * HID + 2 * i], w_hh1[row * HID + 2 * i + 1]);
        }
        #pragma unroll
        for (int i = 0; i < HID / 2; i++)
            wpp[i] = pk2(w_p[2 * i], w_p[2 * i + 1]);
        const float bp = b_p[0];
        float h = 0.f, c = 0.f;

        auto stagex = [&](int xg) {
            const float4* src = (const float4*)(x + (start + (xg << 4)) * INP);
            float4* dst = (float4*)&xbuf[pidx][xg & 1][0];
            dst[lane] = src[lane];                    // float4 0..31
            if (lane < 4) dst[32 + lane] = src[32 + lane];  // float4 32..35
        };

        auto outgroup = [&](int og) {
            if (lane < GROUP) {
                const int t = start + (og << 4) + lane;
                if (t >= out_begin && t < out_end) {
                    const int sl = ((og << 4) + lane) & (RH - 1);
                    const u64* hp = (const u64*)&ringh[pidx][sl][0];
                    u64 a = pk2(0.f, 0.f);
                    #pragma unroll
                    for (int j = 0; j < HID / 2; j++) a = fma2(hp[j], wpp[j], a);
                    float lo, hi; up2(a, lo, hi);
                    out[t] = lo + hi + bp;
                }
            }
        };

        stagex(0);
        __syncwarp();

        for (int g = 0; g < ngroups; g++) {
            if (g + 1 < ngroups) stagex(g + 1);     // consumed next iter (after syncwarp)
            while (*vfB < g - 2) { }                // ring1 slots free
            __threadfence_block();

            const float* xb = &xbuf[pidx][g & 1][0];
            #pragma unroll 2
            for (int i = 0; i < GROUP; i++) {
                const int s = (g << 4) + i;
                float xv[INP];
                #pragma unroll
                for (int j = 0; j < INP; j++) xv[j] = xb[i * INP + j];

                // x projection (registers only)
                u64 xp[4];
                #pragma unroll
                for (int q = 0; q < 4; q++) xp[q] = pk2(xv[2 * q], xv[2 * q + 1]);
                float prg[4];
                #pragma unroll
                for (int gt = 0; gt < 4; gt++) {
                    u64 a = pk2(bb1[gt], 0.f);
                    #pragma unroll
                    for (int q = 0; q < 4; q++) a = fma2(xp[q], wi1p[gt][q], a);
                    float lo, hi; up2(a, lo, hi);
                    prg[gt] = fmaf(xv[8], wi1s[gt], lo + hi);
                }

                // layer-1 recurrence
                u64 acc[4];
                #pragma unroll
                for (int gt = 0; gt < 4; gt++) acc[gt] = pk2(prg[gt], 0.f);
                #pragma unroll
                for (int j = 0; j < HID / 2; j++) {
                    const float h0 = __shfl_sync(0xffffffffu, h, 2 * j);
                    const float h1v = __shfl_sync(0xffffffffu, h, 2 * j + 1);
                    const u64 hp = pk2(h0, h1v);
                    #pragma unroll
                    for (int gt = 0; gt < 4; gt++) acc[gt] = fma2(hp, whhp[gt][j], acc[gt]);
                }
                float pa[4];
                #pragma unroll
                for (int gt = 0; gt < 4; gt++) { float lo, hi; up2(acc[gt], lo, hi); pa[gt] = lo + hi; }

                const float ig = sigf(pa[0]);
                const float fg = sigf(pa[1]);
                const float gg = tanhf_(pa[2]);
                const float og = sigf(pa[3]);
                c = fg * c + ig * gg;
                h = og * tanhf_(c);

                if (active) ring1[pidx][s & (R1 - 1)][k] = h;
            }
            __threadfence_block();
            if (lane == 0) *vfA = g;

            // output projection for previous group (overlaps with B working on group g)
            if (g >= 1) {
                while (*vfB < g - 1) { }
                __threadfence_block();
                outgroup(g - 1);
            }
            __syncwarp();   // xbuf stage visibility
        }
        // final group's outputs
        while (*vfB < ngroups - 1) { }
        __threadfence_block();
        outgroup(ngroups - 1);
    } else {
        // ================= warp B: full layer-2 =================
        u64   wi2p[4][HID / 2], whh2p[4][HID / 2];
        float bb2[4];
        #pragma unroll
        for (int g = 0; g < 4; g++) {
            const int row = g * HID + k;
            #pragma unroll
            for (int i = 0; i < HID / 2; i++) {
                wi2p[g][i]  = pk2(w_ih2[row * HID + 2 * i], w_ih2[row * HID + 2 * i + 1]);
                whh2p[g][i] = pk2(w_hh2[row * HID + 2 * i], w_hh2[row * HID + 2 * i + 1]);
            }
            bb2[g] = b2[row];
        }
        float h = 0.f, c = 0.f;

        for (int g = 0; g < ngroups; g++) {
            while (*vfA < g) { }
            __threadfence_block();

            #pragma unroll 2
            for (int i = 0; i < GROUP; i++) {
                const int s = (g << 4) + i;
                const u64* h1p = (const u64*)&ring1[pidx][s & (R1 - 1)][0];

                u64 acc1[4], acc2[4];
                #pragma unroll
                for (int gt = 0; gt < 4; gt++) { acc1[gt] = pk2(bb2[gt], 0.f); acc2[gt] = pk2(0.f, 0.f); }

                #pragma unroll
                for (int j = 0; j < HID / 2; j++) {
                    const u64 hp1 = h1p[j];
                    #pragma unroll
                    for (int gt = 0; gt < 4; gt++) acc1[gt] = fma2(hp1, wi2p[gt][j], acc1[gt]);
                }
                #pragma unroll
                for (int j = 0; j < HID / 2; j++) {
                    const float h0 = __shfl_sync(0xffffffffu, h, 2 * j);
                    const float h1v = __shfl_sync(0xffffffffu, h, 2 * j + 1);
                    const u64 hp2 = pk2(h0, h1v);
                    #pragma unroll
                    for (int gt = 0; gt < 4; gt++) acc2[gt] = fma2(hp2, whh2p[gt][j], acc2[gt]);
                }
                float pa[4];
                #pragma unroll
                for (int gt = 0; gt < 4; gt++) {
                    float lo1, hi1, lo2, hi2;
                    up2(acc1[gt], lo1, hi1); up2(acc2[gt], lo2, hi2);
                    pa[gt] = (lo1 + hi1) + (lo2 + hi2);
                }

                const float ig = sigf(pa[0]);
                const float fg = sigf(pa[1]);
                const float gg = tanhf_(pa[2]);
                const float og = sigf(pa[3]);
                c = fg * c + ig * gg;
                h = og * tanhf_(c);

                if (active) ringh[pidx][s & (RH - 1)][k] = h;
            }
            __threadfence_block();
            if (lane == 0) *vfB = g;
        }
    }
}

extern "C" void kernel_launch(void* const* d_in, const int* in_sizes, int n_in,
                              void* d_out, int out_size)
{
    const float* x     = (const float*)d_in[0];
    const float* w_ih1 = (const float*)d_in[1];
    const float* w_hh1 = (const float*)d_in[2];
    const float* b1    = (const float*)d_in[3];
    const float* w_ih2 = (const float*)d_in[4];
    const float* w_hh2 = (const float*)d_in[5];
    const float* b2    = (const float*)d_in[6];
    const float* w_p   = (const float*)d_in[7];
    const float* b_p   = (const float*)d_in[8];
    float* out = (float*)d_out;

    lstm_kernel<<<NBLK, 128>>>(x, w_ih1, w_hh1, b1, w_ih2, w_hh2, b2, w_p, b_p, out);
}